// round 2
// baseline (speedup 1.0000x reference)
#include <cuda_runtime.h>
#include <cstdint>

#define NB 64
#define DIN 64
#define DH 128
#define KA 72          // layer-1 K padded (64 x-cols + 3 pos + 5 zero)
#define TM 128         // rows per tile

#define SW1_STRIDE 136
#define SW2_STRIDE 136
#define SA_STRIDE  76
#define SH_STRIDE  132

// smem layout (floats): sW1[72*136]=9792 | sW2[128*136]=17408 | sA[128*76]=9728 | sH[128*132]=16896 | sB[128 ints]
#define OFF_W2 9792
#define OFF_A  27200
#define OFF_H  36928
#define OFF_B  53824
#define SMEM_FLOATS 53952
#define SMEM_BYTES (SMEM_FLOATS*4)

__device__ float g_psum[NB*4];                  // sum x,y,z,count per graph
__device__ unsigned long long g_amin[NB];       // packed (dist2bits<<32 | id)
__device__ int   g_idx[NB];
__device__ float g_cg[NB*DH];                   // per-graph bias for layer-1
__device__ float g_W1e[KA*DH];                  // tf32-rounded effective W1 ([W1b; W1c; 0])
__device__ float g_W2e[DH*DH];                  // tf32-rounded W2

__device__ __forceinline__ unsigned f2tf(float x){
    unsigned u; asm("cvt.rna.tf32.f32 %0, %1;" : "=r"(u) : "f"(x)); return u;
}

__device__ __forceinline__ void atomicMaxF(float* a, float v){
    if (v >= 0.f) atomicMax((int*)a, __float_as_int(v));
    else          atomicMin((unsigned int*)a, __float_as_uint(v));
}

__device__ __forceinline__ void mma8(float (&c)[4], const unsigned (&a)[4], unsigned b0, unsigned b1){
    asm volatile("mma.sync.aligned.m16n8k8.row.col.f32.tf32.tf32.f32 "
        "{%0,%1,%2,%3}, {%4,%5,%6,%7}, {%8,%9}, {%0,%1,%2,%3};\n"
        : "+f"(c[0]), "+f"(c[1]), "+f"(c[2]), "+f"(c[3])
        : "r"(a[0]), "r"(a[1]), "r"(a[2]), "r"(a[3]), "r"(b0), "r"(b1));
}

// ---------------------------------------------------------------------------
__global__ void k_init(float* out, int out_size){
    int i = blockIdx.x*blockDim.x + threadIdx.x;
    if (i < NB*4) g_psum[i] = 0.f;
    if (i < NB)   g_amin[i] = 0xFFFFFFFFFFFFFFFFULL;
    if (i < NB*DH && i < out_size) out[i] = __int_as_float(0xff800000); // -inf
}

// per-graph COM partial sums (warp-uniform reduced atomics; batch is sorted)
__global__ void k_com(const float* __restrict__ pos, const int* __restrict__ batch, int n){
    int i = blockIdx.x*blockDim.x + threadIdx.x;
    int b = -1; float px=0.f, py=0.f, pz=0.f, pc=0.f;
    if (i < n){ b = batch[i]; px = pos[3*i]; py = pos[3*i+1]; pz = pos[3*i+2]; pc = 1.f; }
    int b0 = __shfl_sync(0xffffffffu, b, 0);
    bool uni = __all_sync(0xffffffffu, b == b0);
    if (uni){
        #pragma unroll
        for (int o = 16; o; o >>= 1){
            px += __shfl_down_sync(0xffffffffu, px, o);
            py += __shfl_down_sync(0xffffffffu, py, o);
            pz += __shfl_down_sync(0xffffffffu, pz, o);
            pc += __shfl_down_sync(0xffffffffu, pc, o);
        }
        if ((threadIdx.x & 31) == 0 && b0 >= 0){
            atomicAdd(&g_psum[b0*4+0], px); atomicAdd(&g_psum[b0*4+1], py);
            atomicAdd(&g_psum[b0*4+2], pz); atomicAdd(&g_psum[b0*4+3], pc);
        }
    } else if (b >= 0){
        atomicAdd(&g_psum[b*4+0], px); atomicAdd(&g_psum[b*4+1], py);
        atomicAdd(&g_psum[b*4+2], pz); atomicAdd(&g_psum[b*4+3], pc);
    }
}

// per-graph argmin of dist-to-COM (packed u64 key => first-occurrence min semantics)
__global__ void k_amin(const float* __restrict__ pos, const int* __restrict__ batch, int n){
    int i = blockIdx.x*blockDim.x + threadIdx.x;
    int b = -1; unsigned long long key = 0xFFFFFFFFFFFFFFFFULL;
    if (i < n){
        b = batch[i];
        float cnt = fmaxf(g_psum[b*4+3], 1.f);
        float inv = 1.f / cnt;
        float dx = pos[3*i]   - g_psum[b*4+0]*inv;
        float dy = pos[3*i+1] - g_psum[b*4+1]*inv;
        float dz = pos[3*i+2] - g_psum[b*4+2]*inv;
        float d2 = dx*dx + dy*dy + dz*dz;
        key = ((unsigned long long)__float_as_uint(d2) << 32) | (unsigned)i;
    }
    int b0 = __shfl_sync(0xffffffffu, b, 0);
    bool uni = __all_sync(0xffffffffu, b == b0);
    if (uni){
        #pragma unroll
        for (int o = 16; o; o >>= 1){
            unsigned long long k2 = __shfl_down_sync(0xffffffffu, key, o);
            if (k2 < key) key = k2;
        }
        if ((threadIdx.x & 31) == 0 && b0 >= 0) atomicMin(&g_amin[b0], key);
    } else if (b >= 0){
        atomicMin(&g_amin[b], key);
    }
}

// per-graph bias cg, tf32 weight prep, aux outputs
__global__ void k_prep(const float* __restrict__ x, const float* __restrict__ pos,
                       const int* __restrict__ batch, const float* __restrict__ lf,
                       const float* __restrict__ W1, const float* __restrict__ b1,
                       const float* __restrict__ W2,
                       float* out, int out_size, int n){
    int g = blockIdx.x, c = threadIdx.x;
    __shared__ int sidx;
    if (c == 0){
        int id = (int)(unsigned)(g_amin[g] & 0xFFFFFFFFULL);
        if (id > n-1) id = n-1;
        sidx = id; g_idx[g] = id;
    }
    __syncthreads();
    int idx = sidx;
    // cg = xd @ (W1a - W1b) - pos_dst @ W1c + b1
    float acc = b1[c];
    for (int k = 0; k < DIN; k++)
        acc += x[(size_t)idx*DIN + k] * (W1[k*DH + c] - W1[(DIN+k)*DH + c]);
    for (int j = 0; j < 3; j++)
        acc -= pos[idx*3 + j] * W1[(2*DIN+j)*DH + c];
    g_cg[g*DH + c] = acc;

    if (out_size >= NB*DH + NB*3 + NB + NB*9){
        if (c < 3)  out[NB*DH + g*3 + c] = pos[idx*3 + c];
        if (c == 3) out[NB*DH + NB*3 + g] = (float)batch[idx];
        if (c < 9)  out[NB*DH + NB*3 + NB + g*9 + c] = lf[(size_t)idx*9 + c];
    }
    if (g == 0){
        for (int k = 0; k < DIN; k++) g_W1e[k*DH + c] = __uint_as_float(f2tf(W1[(DIN+k)*DH + c]));
        for (int j = 0; j < 3; j++)   g_W1e[(DIN+j)*DH + c] = __uint_as_float(f2tf(W1[(2*DIN+j)*DH + c]));
        for (int r = DIN+3; r < KA; r++) g_W1e[r*DH + c] = 0.f;
        for (int k = 0; k < DH; k++)  g_W2e[k*DH + c] = __uint_as_float(f2tf(W2[k*DH + c]));
    }
}

// ---------------------------------------------------------------------------
// Main fused kernel: per 128-row tile:
//   h = relu(A[128,72] @ W1e[72,128] + cg[batch])   (TF32 mma, fp32 accum)
//   msg = h @ W2[128,128]
//   segment-max into out (batch sorted -> in-smem column scan + few atomics)
__global__ __launch_bounds__(256, 1) void k_main(
    const float* __restrict__ x, const float* __restrict__ pos,
    const int* __restrict__ batch, const float* __restrict__ b2,
    float* __restrict__ out, int n)
{
    extern __shared__ float sm[];
    float* sW1 = sm;
    float* sW2 = sm + OFF_W2;
    float* sA  = sm + OFF_A;
    float* sH  = sm + OFF_H;
    int*   sB  = (int*)(sm + OFF_B);

    int tid = threadIdx.x;
    for (int i = tid; i < KA*DH; i += 256){ int k = i >> 7, c = i & 127; sW1[k*SW1_STRIDE + c] = g_W1e[i]; }
    for (int i = tid; i < DH*DH; i += 256){ int k = i >> 7, c = i & 127; sW2[k*SW2_STRIDE + c] = g_W2e[i]; }
    float b2c = b2[tid >> 1];

    int warp = tid >> 5, lane = tid & 31, gid = lane >> 2, tig = lane & 3;
    int wm = warp >> 1, wn = warp & 1;           // 4x2 warp grid
    int m0 = wm * 32, n0 = wn * 64;              // warp tile: 32 rows x 64 cols
    int numTiles = (n + TM - 1) / TM;
    __syncthreads();

    for (int t = blockIdx.x; t < numTiles; t += gridDim.x){
        int base = t * TM;
        // ---- load A tile (x as tf32) ----
        for (int i = tid; i < TM*16; i += 256){
            int r = i >> 4, c4 = i & 15; int row = base + r;
            float4 v = make_float4(0.f, 0.f, 0.f, 0.f);
            if (row < n) v = *(const float4*)(x + (size_t)row*DIN + c4*4);
            float* d = sA + r*SA_STRIDE + c4*4;
            d[0] = __uint_as_float(f2tf(v.x)); d[1] = __uint_as_float(f2tf(v.y));
            d[2] = __uint_as_float(f2tf(v.z)); d[3] = __uint_as_float(f2tf(v.w));
        }
        if (tid < TM){
            int row = base + tid; float* d = sA + tid*SA_STRIDE;
            if (row < n){
                d[64] = __uint_as_float(f2tf(pos[3*row]));
                d[65] = __uint_as_float(f2tf(pos[3*row+1]));
                d[66] = __uint_as_float(f2tf(pos[3*row+2]));
                sB[tid] = batch[row];
            } else {
                d[64] = d[65] = d[66] = 0.f; sB[tid] = -1;
            }
            d[67] = d[68] = d[69] = d[70] = d[71] = 0.f;
        }
        __syncthreads();

        // ---- layer 1: acc = A @ W1e ----
        float acc[2][8][4];
        #pragma unroll
        for (int mt = 0; mt < 2; mt++)
            #pragma unroll
            for (int nt = 0; nt < 8; nt++)
                #pragma unroll
                for (int q = 0; q < 4; q++) acc[mt][nt][q] = 0.f;

        #pragma unroll
        for (int ks = 0; ks < 9; ks++){
            int kk = ks * 8;
            unsigned a[2][4];
            #pragma unroll
            for (int mt = 0; mt < 2; mt++){
                const float* ap = sA + (m0 + mt*16 + gid)*SA_STRIDE + kk + tig;
                a[mt][0] = __float_as_uint(ap[0]);
                a[mt][1] = __float_as_uint(ap[8*SA_STRIDE]);
                a[mt][2] = __float_as_uint(ap[4]);
                a[mt][3] = __float_as_uint(ap[8*SA_STRIDE + 4]);
            }
            #pragma unroll
            for (int nt = 0; nt < 8; nt++){
                const float* bp = sW1 + (kk + tig)*SW1_STRIDE + n0 + nt*8 + gid;
                unsigned b0 = __float_as_uint(bp[0]);
                unsigned b1r = __float_as_uint(bp[4*SW1_STRIDE]);
                mma8(acc[0][nt], a[0], b0, b1r);
                mma8(acc[1][nt], a[1], b0, b1r);
            }
        }

        // ---- epilogue 1: h = relu(acc + cg[g]) -> sH (tf32) ----
        #pragma unroll
        for (int mt = 0; mt < 2; mt++){
            int r0 = m0 + mt*16 + gid, r1 = r0 + 8;
            int g0 = sB[r0], g1 = sB[r1];
            const float* cg0 = &g_cg[(g0 >= 0 ? g0 : 0)*DH];
            const float* cg1 = &g_cg[(g1 >= 0 ? g1 : 0)*DH];
            #pragma unroll
            for (int nt = 0; nt < 8; nt++){
                int c0 = n0 + nt*8 + tig*2;
                float v;
                v = acc[mt][nt][0] + (g0 >= 0 ? cg0[c0]   : 0.f);
                sH[r0*SH_STRIDE + c0]     = __uint_as_float(f2tf(fmaxf(v, 0.f)));
                v = acc[mt][nt][1] + (g0 >= 0 ? cg0[c0+1] : 0.f);
                sH[r0*SH_STRIDE + c0 + 1] = __uint_as_float(f2tf(fmaxf(v, 0.f)));
                v = acc[mt][nt][2] + (g1 >= 0 ? cg1[c0]   : 0.f);
                sH[r1*SH_STRIDE + c0]     = __uint_as_float(f2tf(fmaxf(v, 0.f)));
                v = acc[mt][nt][3] + (g1 >= 0 ? cg1[c0+1] : 0.f);
                sH[r1*SH_STRIDE + c0 + 1] = __uint_as_float(f2tf(fmaxf(v, 0.f)));
            }
        }
        __syncthreads();

        // ---- layer 2: acc = h @ W2 ----
        #pragma unroll
        for (int mt = 0; mt < 2; mt++)
            #pragma unroll
            for (int nt = 0; nt < 8; nt++)
                #pragma unroll
                for (int q = 0; q < 4; q++) acc[mt][nt][q] = 0.f;

        #pragma unroll
        for (int ks = 0; ks < 16; ks++){
            int kk = ks * 8;
            unsigned a[2][4];
            #pragma unroll
            for (int mt = 0; mt < 2; mt++){
                const float* ap = sH + (m0 + mt*16 + gid)*SH_STRIDE + kk + tig;
                a[mt][0] = __float_as_uint(ap[0]);
                a[mt][1] = __float_as_uint(ap[8*SH_STRIDE]);
                a[mt][2] = __float_as_uint(ap[4]);
                a[mt][3] = __float_as_uint(ap[8*SH_STRIDE + 4]);
            }
            #pragma unroll
            for (int nt = 0; nt < 8; nt++){
                const float* bp = sW2 + (kk + tig)*SW2_STRIDE + n0 + nt*8 + gid;
                unsigned b0 = __float_as_uint(bp[0]);
                unsigned b1r = __float_as_uint(bp[4*SW2_STRIDE]);
                mma8(acc[0][nt], a[0], b0, b1r);
                mma8(acc[1][nt], a[1], b0, b1r);
            }
        }
        __syncthreads();   // all warps done reading sH before overwrite

        // ---- write raw msg tile into sH ----
        #pragma unroll
        for (int mt = 0; mt < 2; mt++){
            int r0 = m0 + mt*16 + gid, r1 = r0 + 8;
            #pragma unroll
            for (int nt = 0; nt < 8; nt++){
                int c0 = n0 + nt*8 + tig*2;
                sH[r0*SH_STRIDE + c0]     = acc[mt][nt][0];
                sH[r0*SH_STRIDE + c0 + 1] = acc[mt][nt][1];
                sH[r1*SH_STRIDE + c0]     = acc[mt][nt][2];
                sH[r1*SH_STRIDE + c0 + 1] = acc[mt][nt][3];
            }
        }
        __syncthreads();

        // ---- segment-max column scan (batch sorted within tile) ----
        {
            int col = tid >> 1;
            int rs  = (tid & 1) * 64;
            float runmax = __int_as_float(0xff800000);
            int gcur = -1;
            for (int r = rs; r < rs + 64; r++){
                int g = sB[r];
                if (g != gcur){
                    if (gcur >= 0) atomicMaxF(&out[gcur*DH + col], runmax + b2c);
                    gcur = g; runmax = __int_as_float(0xff800000);
                }
                if (g >= 0) runmax = fmaxf(runmax, sH[r*SH_STRIDE + col]);
            }
            if (gcur >= 0) atomicMaxF(&out[gcur*DH + col], runmax + b2c);
        }
        __syncthreads();
    }
}

// ---------------------------------------------------------------------------
extern "C" void kernel_launch(void* const* d_in, const int* in_sizes, int n_in,
                              void* d_out, int out_size){
    const float* x     = (const float*)d_in[0];
    const float* pos   = (const float*)d_in[1];
    const int*   batch = (const int*)  d_in[2];
    const float* lf    = (const float*)d_in[3];
    const float* W1    = (const float*)d_in[4];
    const float* b1    = (const float*)d_in[5];
    const float* W2    = (const float*)d_in[6];
    const float* b2    = (const float*)d_in[7];
    float* out = (float*)d_out;
    int n = in_sizes[2];

    cudaFuncSetAttribute(k_main, cudaFuncAttributeMaxDynamicSharedMemorySize, SMEM_BYTES);

    k_init<<<32, 256>>>(out, out_size);
    int nb = (n + 255) / 256;
    k_com<<<nb, 256>>>(pos, batch, n);
    k_amin<<<nb, 256>>>(pos, batch, n);
    k_prep<<<NB, DH>>>(x, pos, batch, lf, W1, b1, W2, out, out_size, n);
    k_main<<<148, 256, SMEM_BYTES>>>(x, pos, batch, b2, out, n);
}

// round 3
// speedup vs baseline: 1.0142x; 1.0142x over previous
#include <cuda_runtime.h>
#include <cstdint>

#define NB 64
#define DIN 64
#define DH 128
#define KA 72          // layer-1 K padded (64 x-cols + 3 pos + 5 zero)
#define TM 128         // rows per tile

#define SW1_STRIDE 136
#define SW2_STRIDE 136
#define SA_STRIDE  76
#define SH_STRIDE  132

// smem layout (floats): sW1[72*136]=9792 | sW2[128*136]=17408 | sA[128*76]=9728 | sH[128*132]=16896 | sB[128 ints]
#define OFF_W2 9792
#define OFF_A  27200
#define OFF_H  36928
#define OFF_B  53824
#define SMEM_FLOATS 53952
#define SMEM_BYTES (SMEM_FLOATS*4)

__device__ float g_psum[NB*4];                  // sum x,y,z,count per graph
__device__ unsigned long long g_amin[NB];       // packed (dist2bits<<32 | id)
__device__ int   g_idx[NB];
__device__ float g_cg[NB*DH];                   // per-graph bias for layer-1
__device__ float g_W1e[KA*DH];                  // tf32-rounded effective W1 ([W1b; W1c; 0])
__device__ float g_W2e[DH*DH];                  // tf32-rounded W2

__device__ __forceinline__ unsigned f2tf(float x){
    unsigned u; asm("cvt.rna.tf32.f32 %0, %1;" : "=r"(u) : "f"(x)); return u;
}

__device__ __forceinline__ void atomicMaxF(float* a, float v){
    if (v >= 0.f) atomicMax((int*)a, __float_as_int(v));
    else          atomicMin((unsigned int*)a, __float_as_uint(v));
}

__device__ __forceinline__ void mma8(float (&c)[4], const unsigned (&a)[4], unsigned b0, unsigned b1){
    asm volatile("mma.sync.aligned.m16n8k8.row.col.f32.tf32.tf32.f32 "
        "{%0,%1,%2,%3}, {%4,%5,%6,%7}, {%8,%9}, {%0,%1,%2,%3};\n"
        : "+f"(c[0]), "+f"(c[1]), "+f"(c[2]), "+f"(c[3])
        : "r"(a[0]), "r"(a[1]), "r"(a[2]), "r"(a[3]), "r"(b0), "r"(b1));
}

// ---------------------------------------------------------------------------
__global__ void k_init(float* out, int out_size){
    int i = blockIdx.x*blockDim.x + threadIdx.x;
    if (i < NB*4) g_psum[i] = 0.f;
    if (i < NB)   g_amin[i] = 0xFFFFFFFFFFFFFFFFULL;
    if (i < NB*DH && i < out_size) out[i] = __int_as_float(0xff800000); // -inf
}

// per-graph COM partial sums (warp-uniform reduced atomics; batch is sorted)
__global__ void k_com(const float* __restrict__ pos, const int* __restrict__ batch, int n){
    int i = blockIdx.x*blockDim.x + threadIdx.x;
    int b = -1; float px=0.f, py=0.f, pz=0.f, pc=0.f;
    if (i < n){ b = batch[i]; px = pos[3*i]; py = pos[3*i+1]; pz = pos[3*i+2]; pc = 1.f; }
    int b0 = __shfl_sync(0xffffffffu, b, 0);
    bool uni = __all_sync(0xffffffffu, b == b0);
    if (uni){
        #pragma unroll
        for (int o = 16; o; o >>= 1){
            px += __shfl_down_sync(0xffffffffu, px, o);
            py += __shfl_down_sync(0xffffffffu, py, o);
            pz += __shfl_down_sync(0xffffffffu, pz, o);
            pc += __shfl_down_sync(0xffffffffu, pc, o);
        }
        if ((threadIdx.x & 31) == 0 && b0 >= 0){
            atomicAdd(&g_psum[b0*4+0], px); atomicAdd(&g_psum[b0*4+1], py);
            atomicAdd(&g_psum[b0*4+2], pz); atomicAdd(&g_psum[b0*4+3], pc);
        }
    } else if (b >= 0){
        atomicAdd(&g_psum[b*4+0], px); atomicAdd(&g_psum[b*4+1], py);
        atomicAdd(&g_psum[b*4+2], pz); atomicAdd(&g_psum[b*4+3], pc);
    }
}

// per-graph argmin of dist-to-COM (packed u64 key => first-occurrence min semantics)
__global__ void k_amin(const float* __restrict__ pos, const int* __restrict__ batch, int n){
    int i = blockIdx.x*blockDim.x + threadIdx.x;
    int b = -1; unsigned long long key = 0xFFFFFFFFFFFFFFFFULL;
    if (i < n){
        b = batch[i];
        float cnt = fmaxf(g_psum[b*4+3], 1.f);
        float inv = 1.f / cnt;
        float dx = pos[3*i]   - g_psum[b*4+0]*inv;
        float dy = pos[3*i+1] - g_psum[b*4+1]*inv;
        float dz = pos[3*i+2] - g_psum[b*4+2]*inv;
        float d2 = dx*dx + dy*dy + dz*dz;
        key = ((unsigned long long)__float_as_uint(d2) << 32) | (unsigned)i;
    }
    int b0 = __shfl_sync(0xffffffffu, b, 0);
    bool uni = __all_sync(0xffffffffu, b == b0);
    if (uni){
        #pragma unroll
        for (int o = 16; o; o >>= 1){
            unsigned long long k2 = __shfl_down_sync(0xffffffffu, key, o);
            if (k2 < key) key = k2;
        }
        if ((threadIdx.x & 31) == 0 && b0 >= 0) atomicMin(&g_amin[b0], key);
    } else if (b >= 0){
        atomicMin(&g_amin[b], key);
    }
}

// per-graph bias cg, tf32 weight prep, aux outputs
__global__ void k_prep(const float* __restrict__ x, const float* __restrict__ pos,
                       const int* __restrict__ batch, const float* __restrict__ lf,
                       const float* __restrict__ W1, const float* __restrict__ b1,
                       const float* __restrict__ W2,
                       float* out, int out_size, int n){
    int g = blockIdx.x, c = threadIdx.x;
    __shared__ int sidx;
    if (c == 0){
        int id = (int)(unsigned)(g_amin[g] & 0xFFFFFFFFULL);
        if (id > n-1) id = n-1;
        sidx = id; g_idx[g] = id;
    }
    __syncthreads();
    int idx = sidx;
    // cg = xd @ (W1a - W1b) - pos_dst @ W1c + b1
    float acc = b1[c];
    for (int k = 0; k < DIN; k++)
        acc += x[(size_t)idx*DIN + k] * (W1[k*DH + c] - W1[(DIN+k)*DH + c]);
    for (int j = 0; j < 3; j++)
        acc -= pos[idx*3 + j] * W1[(2*DIN+j)*DH + c];
    g_cg[g*DH + c] = acc;

    if (out_size >= NB*DH + NB*3 + NB + NB*9){
        if (c < 3)  out[NB*DH + g*3 + c] = pos[idx*3 + c];
        if (c == 3) out[NB*DH + NB*3 + g] = (float)batch[idx];
        if (c < 9)  out[NB*DH + NB*3 + NB + g*9 + c] = lf[(size_t)idx*9 + c];
    }
    if (g == 0){
        for (int k = 0; k < DIN; k++) g_W1e[k*DH + c] = __uint_as_float(f2tf(W1[(DIN+k)*DH + c]));
        for (int j = 0; j < 3; j++)   g_W1e[(DIN+j)*DH + c] = __uint_as_float(f2tf(W1[(2*DIN+j)*DH + c]));
        for (int r = DIN+3; r < KA; r++) g_W1e[r*DH + c] = 0.f;
        for (int k = 0; k < DH; k++)  g_W2e[k*DH + c] = __uint_as_float(f2tf(W2[k*DH + c]));
    }
}

// ---------------------------------------------------------------------------
// Main fused kernel: per 128-row tile:
//   h = relu(A[128,72] @ W1e[72,128] + cg[batch])   (TF32 mma, fp32 accum)
//   msg = h @ W2[128,128]
//   segment-max into out (batch sorted -> in-smem column scan + few atomics)
__global__ __launch_bounds__(256, 1) void k_main(
    const float* __restrict__ x, const float* __restrict__ pos,
    const int* __restrict__ batch, const float* __restrict__ b2,
    float* __restrict__ out, int n)
{
    extern __shared__ float sm[];
    float* sW1 = sm;
    float* sW2 = sm + OFF_W2;
    float* sA  = sm + OFF_A;
    float* sH  = sm + OFF_H;
    int*   sB  = (int*)(sm + OFF_B);

    int tid = threadIdx.x;
    for (int i = tid; i < KA*DH; i += 256){ int k = i >> 7, c = i & 127; sW1[k*SW1_STRIDE + c] = g_W1e[i]; }
    for (int i = tid; i < DH*DH; i += 256){ int k = i >> 7, c = i & 127; sW2[k*SW2_STRIDE + c] = g_W2e[i]; }
    float b2c = b2[tid >> 1];

    int warp = tid >> 5, lane = tid & 31, gid = lane >> 2, tig = lane & 3;
    int wm = warp >> 1, wn = warp & 1;           // 4x2 warp grid
    int m0 = wm * 32, n0 = wn * 64;              // warp tile: 32 rows x 64 cols
    int numTiles = (n + TM - 1) / TM;
    __syncthreads();

    for (int t = blockIdx.x; t < numTiles; t += gridDim.x){
        int base = t * TM;
        // ---- load A tile (x as tf32) ----
        for (int i = tid; i < TM*16; i += 256){
            int r = i >> 4, c4 = i & 15; int row = base + r;
            float4 v = make_float4(0.f, 0.f, 0.f, 0.f);
            if (row < n) v = *(const float4*)(x + (size_t)row*DIN + c4*4);
            float* d = sA + r*SA_STRIDE + c4*4;
            d[0] = __uint_as_float(f2tf(v.x)); d[1] = __uint_as_float(f2tf(v.y));
            d[2] = __uint_as_float(f2tf(v.z)); d[3] = __uint_as_float(f2tf(v.w));
        }
        if (tid < TM){
            int row = base + tid; float* d = sA + tid*SA_STRIDE;
            if (row < n){
                d[64] = __uint_as_float(f2tf(pos[3*row]));
                d[65] = __uint_as_float(f2tf(pos[3*row+1]));
                d[66] = __uint_as_float(f2tf(pos[3*row+2]));
                sB[tid] = batch[row];
            } else {
                d[64] = d[65] = d[66] = 0.f; sB[tid] = -1;
            }
            d[67] = d[68] = d[69] = d[70] = d[71] = 0.f;
        }
        __syncthreads();

        // ---- layer 1: acc = A @ W1e ----
        float acc[2][8][4];
        #pragma unroll
        for (int mt = 0; mt < 2; mt++)
            #pragma unroll
            for (int nt = 0; nt < 8; nt++)
                #pragma unroll
                for (int q = 0; q < 4; q++) acc[mt][nt][q] = 0.f;

        #pragma unroll
        for (int ks = 0; ks < 9; ks++){
            int kk = ks * 8;
            unsigned a[2][4];
            #pragma unroll
            for (int mt = 0; mt < 2; mt++){
                const float* ap = sA + (m0 + mt*16 + gid)*SA_STRIDE + kk + tig;
                a[mt][0] = __float_as_uint(ap[0]);
                a[mt][1] = __float_as_uint(ap[8*SA_STRIDE]);
                a[mt][2] = __float_as_uint(ap[4]);
                a[mt][3] = __float_as_uint(ap[8*SA_STRIDE + 4]);
            }
            #pragma unroll
            for (int nt = 0; nt < 8; nt++){
                const float* bp = sW1 + (kk + tig)*SW1_STRIDE + n0 + nt*8 + gid;
                unsigned b0 = __float_as_uint(bp[0]);
                unsigned b1r = __float_as_uint(bp[4*SW1_STRIDE]);
                mma8(acc[0][nt], a[0], b0, b1r);
                mma8(acc[1][nt], a[1], b0, b1r);
            }
        }

        // ---- epilogue 1: h = relu(acc + cg[g]) -> sH (tf32) ----
        #pragma unroll
        for (int mt = 0; mt < 2; mt++){
            int r0 = m0 + mt*16 + gid, r1 = r0 + 8;
            int g0 = sB[r0], g1 = sB[r1];
            const float* cg0 = &g_cg[(g0 >= 0 ? g0 : 0)*DH];
            const float* cg1 = &g_cg[(g1 >= 0 ? g1 : 0)*DH];
            #pragma unroll
            for (int nt = 0; nt < 8; nt++){
                int c0 = n0 + nt*8 + tig*2;
                float v;
                v = acc[mt][nt][0] + (g0 >= 0 ? cg0[c0]   : 0.f);
                sH[r0*SH_STRIDE + c0]     = __uint_as_float(f2tf(fmaxf(v, 0.f)));
                v = acc[mt][nt][1] + (g0 >= 0 ? cg0[c0+1] : 0.f);
                sH[r0*SH_STRIDE + c0 + 1] = __uint_as_float(f2tf(fmaxf(v, 0.f)));
                v = acc[mt][nt][2] + (g1 >= 0 ? cg1[c0]   : 0.f);
                sH[r1*SH_STRIDE + c0]     = __uint_as_float(f2tf(fmaxf(v, 0.f)));
                v = acc[mt][nt][3] + (g1 >= 0 ? cg1[c0+1] : 0.f);
                sH[r1*SH_STRIDE + c0 + 1] = __uint_as_float(f2tf(fmaxf(v, 0.f)));
            }
        }
        __syncthreads();

        // ---- layer 2: acc = h @ W2 ----
        #pragma unroll
        for (int mt = 0; mt < 2; mt++)
            #pragma unroll
            for (int nt = 0; nt < 8; nt++)
                #pragma unroll
                for (int q = 0; q < 4; q++) acc[mt][nt][q] = 0.f;

        #pragma unroll
        for (int ks = 0; ks < 16; ks++){
            int kk = ks * 8;
            unsigned a[2][4];
            #pragma unroll
            for (int mt = 0; mt < 2; mt++){
                const float* ap = sH + (m0 + mt*16 + gid)*SH_STRIDE + kk + tig;
                a[mt][0] = __float_as_uint(ap[0]);
                a[mt][1] = __float_as_uint(ap[8*SH_STRIDE]);
                a[mt][2] = __float_as_uint(ap[4]);
                a[mt][3] = __float_as_uint(ap[8*SH_STRIDE + 4]);
            }
            #pragma unroll
            for (int nt = 0; nt < 8; nt++){
                const float* bp = sW2 + (kk + tig)*SW2_STRIDE + n0 + nt*8 + gid;
                unsigned b0 = __float_as_uint(bp[0]);
                unsigned b1r = __float_as_uint(bp[4*SW2_STRIDE]);
                mma8(acc[0][nt], a[0], b0, b1r);
                mma8(acc[1][nt], a[1], b0, b1r);
            }
        }
        __syncthreads();   // all warps done reading sH before overwrite

        // ---- write raw msg tile into sH ----
        #pragma unroll
        for (int mt = 0; mt < 2; mt++){
            int r0 = m0 + mt*16 + gid, r1 = r0 + 8;
            #pragma unroll
            for (int nt = 0; nt < 8; nt++){
                int c0 = n0 + nt*8 + tig*2;
                sH[r0*SH_STRIDE + c0]     = acc[mt][nt][0];
                sH[r0*SH_STRIDE + c0 + 1] = acc[mt][nt][1];
                sH[r1*SH_STRIDE + c0]     = acc[mt][nt][2];
                sH[r1*SH_STRIDE + c0 + 1] = acc[mt][nt][3];
            }
        }
        __syncthreads();

        // ---- segment-max column scan (batch sorted within tile) ----
        {
            int col = tid >> 1;
            int rs  = (tid & 1) * 64;
            float runmax = __int_as_float(0xff800000);
            int gcur = -1;
            for (int r = rs; r < rs + 64; r++){
                int g = sB[r];
                if (g != gcur){
                    if (gcur >= 0) atomicMaxF(&out[gcur*DH + col], runmax + b2c);
                    gcur = g; runmax = __int_as_float(0xff800000);
                }
                if (g >= 0) runmax = fmaxf(runmax, sH[r*SH_STRIDE + col]);
            }
            if (gcur >= 0) atomicMaxF(&out[gcur*DH + col], runmax + b2c);
        }
        __syncthreads();
    }
}

// ---------------------------------------------------------------------------
extern "C" void kernel_launch(void* const* d_in, const int* in_sizes, int n_in,
                              void* d_out, int out_size){
    const float* x     = (const float*)d_in[0];
    const float* pos   = (const float*)d_in[1];
    const int*   batch = (const int*)  d_in[2];
    const float* lf    = (const float*)d_in[3];
    const float* W1    = (const float*)d_in[4];
    const float* b1    = (const float*)d_in[5];
    const float* W2    = (const float*)d_in[6];
    const float* b2    = (const float*)d_in[7];
    float* out = (float*)d_out;
    int n = in_sizes[2];

    cudaFuncSetAttribute(k_main, cudaFuncAttributeMaxDynamicSharedMemorySize, SMEM_BYTES);

    k_init<<<32, 256>>>(out, out_size);
    int nb = (n + 255) / 256;
    k_com<<<nb, 256>>>(pos, batch, n);
    k_amin<<<nb, 256>>>(pos, batch, n);
    k_prep<<<NB, DH>>>(x, pos, batch, lf, W1, b1, W2, out, out_size, n);
    k_main<<<148, 256, SMEM_BYTES>>>(x, pos, batch, b2, out, n);
}